// round 4
// baseline (speedup 1.0000x reference)
#include <cuda_runtime.h>
#include <cstdint>

#define NS 65536
#define D  32
#define R  128
#define S  8          // samples per warp
#define WPB 8         // warps per block

typedef unsigned long long ull;

// smem: sW[D*R]@0, sV[D*R]@16384, sC[D*R]@32768, sB[R]@49152, x tile@49664
#define OFF_V_IMM 16384
#define OFF_C_IMM 32768
#define OFF_B  49152
#define OFF_X  49664
#define SMEM_BYTES (49664 + WPB * D * S * 8)

__device__ float gW[D * R];
__device__ float gV[D * R];
__device__ float gC[D * R];
__device__ float gBias[R];

__global__ void anfis_precomp(const float* __restrict__ a,
                              const float* __restrict__ b,
                              const float* __restrict__ c) {
    int r = blockIdx.x, d = threadIdx.x;
    float av = a[r * D + d];
    float bv = fmaxf(b[r * D + d], 1e-8f);
    float w  = 0.70710678118654752f / bv;
    gW[d * R + r] = w;
    gV[d * R + r] = -w * av;
    gC[d * R + r] = c[r * (D + 1) + d];
    if (d == 0) gBias[r] = c[r * (D + 1) + D];
}

__device__ __forceinline__ ull fma2(ull a, ull b, ull c) {
    ull d;
    asm("fma.rn.f32x2 %0, %1, %2, %3;" : "=l"(d) : "l"(a), "l"(b), "l"(c));
    return d;
}
// 16B shared load at base + compile-time immediate
#define LDS128I(base, imm, lo, hi) \
    asm volatile("ld.shared.v2.u64 {%0, %1}, [%2 + %3];" \
                 : "=l"(lo), "=l"(hi) : "r"(base), "n"(imm))

__device__ __forceinline__ void lds128(uint32_t addr, ull& lo, ull& hi) {
    asm volatile("ld.shared.v2.u64 {%0, %1}, [%2];" : "=l"(lo), "=l"(hi) : "r"(addr));
}
__device__ __forceinline__ void sts64(uint32_t addr, float lo, float hi) {
    asm volatile("st.shared.v2.f32 [%0], {%1, %2};" :: "r"(addr), "f"(lo), "f"(hi));
}
__device__ __forceinline__ void unpack2(ull v, float& lo, float& hi) {
    asm("mov.b64 {%0, %1}, %2;" : "=f"(lo), "=f"(hi) : "l"(v));
}

__global__ void __launch_bounds__(256, 3)
anfis_main(const float* __restrict__ X,
           float* __restrict__ pred,
           float* __restrict__ strengths,
           float* __restrict__ normalized) {
    extern __shared__ float smem[];
    uint32_t sbase;
    {
        uint64_t t;
        asm("cvta.to.shared.u64 %0, %1;" : "=l"(t) : "l"(smem));
        sbase = (uint32_t)t;
    }

    for (int i = threadIdx.x; i < D * R; i += blockDim.x) {
        smem[i]                    = gW[i];
        smem[OFF_V_IMM / 4 + i]    = gV[i];
        smem[OFF_C_IMM / 4 + i]    = gC[i];
    }
    if (threadIdx.x < R) smem[OFF_B / 4 + threadIdx.x] = gBias[threadIdx.x];
    __syncthreads();

    const int lane = threadIdx.x & 31;
    const int warp = threadIdx.x >> 5;
    const int rb   = lane * 4;
    const int n0   = (blockIdx.x * WPB + warp) * S;

    // single coefficient base; w/v/c reached via immediate offsets
    const uint32_t cfA = sbase + rb * 4;
    const uint32_t xA  = sbase + OFF_X + warp * (D * S * 8);

    // ---- stage 8 rows of X as duplicated (x,x) pairs, layout [d][s]
    {
        #pragma unroll
        for (int half = 0; half < 2; half++) {
            int j   = lane + half * 32;
            int row = j >> 3;
            int seg = j & 7;
            float4 v = *reinterpret_cast<const float4*>(X + (n0 + row) * D + seg * 4);
            uint32_t base = xA + ((seg * 4) * S + row) * 8;
            sts64(base + 0 * S * 8, v.x, v.x);
            sts64(base + 1 * S * 8, v.y, v.y);
            sts64(base + 2 * S * 8, v.z, v.z);
            sts64(base + 3 * S * 8, v.w, v.w);
        }
        __syncwarp();
    }

    // ---- accumulators (fused): ag = sum u^2, al = consequent
    ull bb01, bb23;
    lds128(sbase + OFF_B + rb * 4, bb01, bb23);
    ull ag[S][2], al[S][2];
    #pragma unroll
    for (int s = 0; s < S; s++) {
        ag[s][0] = 0ull; ag[s][1] = 0ull;
        al[s][0] = bb01; al[s][1] = bb23;
    }

    uint32_t cf = cfA;   // advances 512B per d
    uint32_t xb = xA;    // advances 64B per d
    #pragma unroll 8
    for (int d = 0; d < D; d++) {
        ull w01, w23, v01, v23, c01, c23;
        LDS128I(cf, 0,         w01, w23);
        LDS128I(cf, OFF_V_IMM, v01, v23);
        LDS128I(cf, OFF_C_IMM, c01, c23);
        #pragma unroll
        for (int p = 0; p < S / 2; p++) {
            ull xa, xc;
            LDS128I(xb, 0, xa, xc);  // two samples, each duplicated — but p varies
            // p-dependent immediate handled below instead
            (void)xa; (void)xc;
        }
        // NOTE: replaced above placeholder with explicit p-unrolled loads:
        {
            ull xa, xc;
            LDS128I(xb, 0,  xa, xc);
            ull u0 = fma2(w01, xa, v01), u1 = fma2(w23, xa, v23);
            ag[0][0] = fma2(u0, u0, ag[0][0]); ag[0][1] = fma2(u1, u1, ag[0][1]);
            al[0][0] = fma2(c01, xa, al[0][0]); al[0][1] = fma2(c23, xa, al[0][1]);
            ull u2 = fma2(w01, xc, v01), u3 = fma2(w23, xc, v23);
            ag[1][0] = fma2(u2, u2, ag[1][0]); ag[1][1] = fma2(u3, u3, ag[1][1]);
            al[1][0] = fma2(c01, xc, al[1][0]); al[1][1] = fma2(c23, xc, al[1][1]);
        }
        {
            ull xa, xc;
            LDS128I(xb, 16, xa, xc);
            ull u0 = fma2(w01, xa, v01), u1 = fma2(w23, xa, v23);
            ag[2][0] = fma2(u0, u0, ag[2][0]); ag[2][1] = fma2(u1, u1, ag[2][1]);
            al[2][0] = fma2(c01, xa, al[2][0]); al[2][1] = fma2(c23, xa, al[2][1]);
            ull u2 = fma2(w01, xc, v01), u3 = fma2(w23, xc, v23);
            ag[3][0] = fma2(u2, u2, ag[3][0]); ag[3][1] = fma2(u3, u3, ag[3][1]);
            al[3][0] = fma2(c01, xc, al[3][0]); al[3][1] = fma2(c23, xc, al[3][1]);
        }
        {
            ull xa, xc;
            LDS128I(xb, 32, xa, xc);
            ull u0 = fma2(w01, xa, v01), u1 = fma2(w23, xa, v23);
            ag[4][0] = fma2(u0, u0, ag[4][0]); ag[4][1] = fma2(u1, u1, ag[4][1]);
            al[4][0] = fma2(c01, xa, al[4][0]); al[4][1] = fma2(c23, xa, al[4][1]);
            ull u2 = fma2(w01, xc, v01), u3 = fma2(w23, xc, v23);
            ag[5][0] = fma2(u2, u2, ag[5][0]); ag[5][1] = fma2(u3, u3, ag[5][1]);
            al[5][0] = fma2(c01, xc, al[5][0]); al[5][1] = fma2(c23, xc, al[5][1]);
        }
        {
            ull xa, xc;
            LDS128I(xb, 48, xa, xc);
            ull u0 = fma2(w01, xa, v01), u1 = fma2(w23, xa, v23);
            ag[6][0] = fma2(u0, u0, ag[6][0]); ag[6][1] = fma2(u1, u1, ag[6][1]);
            al[6][0] = fma2(c01, xa, al[6][0]); al[6][1] = fma2(c23, xa, al[6][1]);
            ull u2 = fma2(w01, xc, v01), u3 = fma2(w23, xc, v23);
            ag[7][0] = fma2(u2, u2, ag[7][0]); ag[7][1] = fma2(u3, u3, ag[7][1]);
            al[7][0] = fma2(c01, xc, al[7][0]); al[7][1] = fma2(c23, xc, al[7][1]);
        }
        cf += R * 4;     // 512
        xb += S * 8;     // 64
    }

    // ---- epilogue: exp, reductions, stores
    #pragma unroll
    for (int s = 0; s < S; s++) {
        float e0, e1, e2, e3, r0, r1, r2, r3;
        unpack2(ag[s][0], e0, e1);
        unpack2(ag[s][1], e2, e3);
        unpack2(al[s][0], r0, r1);
        unpack2(al[s][1], r2, r3);
        float s0 = __expf(-e0), s1 = __expf(-e1);
        float s2 = __expf(-e2), s3 = __expf(-e3);

        float ssum = (s0 + s1) + (s2 + s3);
        float sp   = (s0 * r0 + s1 * r1) + (s2 * r2 + s3 * r3);
        #pragma unroll
        for (int off = 16; off > 0; off >>= 1) {
            ssum += __shfl_xor_sync(0xffffffffu, ssum, off);
            sp   += __shfl_xor_sync(0xffffffffu, sp,   off);
        }
        const float inv = 1.0f / (ssum + 1e-8f);

        const int base = (n0 + s) * R + rb;
        *reinterpret_cast<float4*>(&strengths[base])  = make_float4(s0, s1, s2, s3);
        *reinterpret_cast<float4*>(&normalized[base]) =
            make_float4(s0 * inv, s1 * inv, s2 * inv, s3 * inv);
        if (lane == 0) pred[n0 + s] = sp * inv;
    }
}

extern "C" void kernel_launch(void* const* d_in, const int* in_sizes, int n_in,
                              void* d_out, int out_size) {
    const float* X = (const float*)d_in[0];
    const float* a = (const float*)d_in[1];
    const float* b = (const float*)d_in[2];
    const float* c = (const float*)d_in[3];

    float* out        = (float*)d_out;
    float* pred       = out;
    float* strengths  = out + NS;
    float* normalized = out + NS + NS * R;

    static bool attr_set = false;
    if (!attr_set) {
        cudaFuncSetAttribute(anfis_main,
                             cudaFuncAttributeMaxDynamicSharedMemorySize,
                             SMEM_BYTES);
        attr_set = true;
    }

    anfis_precomp<<<R, D>>>(a, b, c);
    anfis_main<<<NS / S / WPB, 256, SMEM_BYTES>>>(X, pred, strengths, normalized);
}

// round 5
// speedup vs baseline: 2.4374x; 2.4374x over previous
#include <cuda_runtime.h>
#include <cstdint>

#define NS 65536
#define D  32
#define R  128
#define S  8          // samples per group
#define GPB 4         // groups per block (2 warps each -> 8 warps, 256 threads)

typedef unsigned long long ull;

// smem layout (bytes):
//   sWV  [D][64 pairs][w0,w1,v0,v1] @ 0       (32768)
//   sC   [D][R]                    @ 32768    (16384)
//   sB   [R]                       @ 49152    (512)
//   red  [GPB][S][2 halves][2]     @ 49664    (512)
//   xt   [GPB][D][S] ull           @ 50176    (8192)  x duplicated (x,x)
#define OFF_WV  0
#define OFF_C   32768
#define OFF_B   49152
#define OFF_RED 49664
#define OFF_X   50176
#define SMEM_BYTES (50176 + GPB * D * S * 8)

__device__ float gWV[D * 64 * 4];
__device__ float gC[D * R];
__device__ float gBias[R];

__global__ void anfis_precomp(const float* __restrict__ a,
                              const float* __restrict__ b,
                              const float* __restrict__ c) {
    int r = blockIdx.x, d = threadIdx.x;
    float av = a[r * D + d];
    float bv = fmaxf(b[r * D + d], 1e-8f);
    float w  = 0.70710678118654752f / bv;
    int p = r >> 1, e = r & 1;
    gWV[(d * 64 + p) * 4 + e]     = w;        // (w0,w1,v0,v1) per pair
    gWV[(d * 64 + p) * 4 + 2 + e] = -w * av;
    gC[d * R + r] = c[r * (D + 1) + d];
    if (d == 0) gBias[r] = c[r * (D + 1) + D];
}

__device__ __forceinline__ ull fma2(ull a, ull b, ull c) {
    ull d;
    asm("fma.rn.f32x2 %0, %1, %2, %3;" : "=l"(d) : "l"(a), "l"(b), "l"(c));
    return d;
}
#define LDS128I(base, imm, lo, hi) \
    asm volatile("ld.shared.v2.u64 {%0, %1}, [%2 + %3];" \
                 : "=l"(lo), "=l"(hi) : "r"(base), "n"(imm))
__device__ __forceinline__ ull lds64(uint32_t addr) {
    ull v;
    asm volatile("ld.shared.u64 %0, [%1];" : "=l"(v) : "r"(addr));
    return v;
}
__device__ __forceinline__ void sts64(uint32_t addr, float lo, float hi) {
    asm volatile("st.shared.v2.f32 [%0], {%1, %2};" :: "r"(addr), "f"(lo), "f"(hi));
}
__device__ __forceinline__ void unpack2(ull v, float& lo, float& hi) {
    asm("mov.b64 {%0, %1}, %2;" : "=f"(lo), "=f"(hi) : "l"(v));
}
__device__ __forceinline__ ull pack2(float lo, float hi) {
    ull v;
    asm("mov.b64 %0, {%1, %2};" : "=l"(v) : "f"(lo), "f"(hi));
    return v;
}

__global__ void __launch_bounds__(256, 3)
anfis_main(const float* __restrict__ X,
           float* __restrict__ pred,
           float* __restrict__ strengths,
           float* __restrict__ normalized) {
    extern __shared__ float smem[];
    uint32_t sbase;
    {
        uint64_t t;
        asm("cvta.to.shared.u64 %0, %1;" : "=l"(t) : "l"(smem));
        sbase = (uint32_t)t;
    }

    // cooperative table fill
    for (int i = threadIdx.x; i < D * 64 * 4; i += blockDim.x)
        smem[OFF_WV / 4 + i] = gWV[i];
    for (int i = threadIdx.x; i < D * R; i += blockDim.x)
        smem[OFF_C / 4 + i] = gC[i];
    if (threadIdx.x < R) smem[OFF_B / 4 + threadIdx.x] = gBias[threadIdx.x];

    // stage X: thread t handles float4 j=t&63 of group g=t>>6
    {
        int g   = threadIdx.x >> 6;
        int j   = threadIdx.x & 63;
        int row = j >> 3;
        int seg = j & 7;
        int n0g = (blockIdx.x * GPB + g) * S;
        float4 v = *reinterpret_cast<const float4*>(X + (n0g + row) * D + seg * 4);
        uint32_t base = sbase + OFF_X + g * (D * S * 8) + ((seg * 4) * S + row) * 8;
        sts64(base + 0 * S * 8, v.x, v.x);
        sts64(base + 1 * S * 8, v.y, v.y);
        sts64(base + 2 * S * 8, v.z, v.z);
        sts64(base + 3 * S * 8, v.w, v.w);
    }
    __syncthreads();

    const int lane = threadIdx.x & 31;
    const int warp = threadIdx.x >> 5;
    const int g    = warp >> 1;          // group in block
    const int half = warp & 1;           // rule half: 0 -> rules 0-63, 1 -> 64-127
    const int rb   = half * 64 + lane * 2;
    const int n0   = (blockIdx.x * GPB + g) * S;

    uint32_t wvA = sbase + OFF_WV + (half * 32 + lane) * 16;  // +1024/d
    uint32_t cA  = sbase + OFF_C + rb * 4;                    // +512/d
    uint32_t xb  = sbase + OFF_X + g * (D * S * 8);           // +64/d

    ull bb = lds64(sbase + OFF_B + rb * 4);
    ull ag[S], al[S];
    #pragma unroll
    for (int s = 0; s < S; s++) { ag[s] = 0ull; al[s] = bb; }

    #pragma unroll 8
    for (int d = 0; d < D; d++) {
        ull w01, v01;
        LDS128I(wvA, 0, w01, v01);
        ull c01 = lds64(cA);
        #pragma unroll
        for (int p = 0; p < 4; p++) {
            ull xa, xc;
            switch (p) {   // compile-time immediates
            case 0: LDS128I(xb, 0,  xa, xc); break;
            case 1: LDS128I(xb, 16, xa, xc); break;
            case 2: LDS128I(xb, 32, xa, xc); break;
            default: LDS128I(xb, 48, xa, xc); break;
            }
            ull ua = fma2(w01, xa, v01);
            ag[2 * p]     = fma2(ua, ua, ag[2 * p]);
            al[2 * p]     = fma2(c01, xa, al[2 * p]);
            ull uc = fma2(w01, xc, v01);
            ag[2 * p + 1] = fma2(uc, uc, ag[2 * p + 1]);
            al[2 * p + 1] = fma2(c01, xc, al[2 * p + 1]);
        }
        wvA += 64 * 16;   // 1024
        cA  += R * 4;     // 512
        xb  += S * 8;     // 64
    }

    // ---- per-warp partial reductions + strengths stores
    const uint32_t redA = sbase + OFF_RED + (g * 32) * 4;
    #pragma unroll
    for (int s = 0; s < S; s++) {
        float e0, e1, r0, r1;
        unpack2(ag[s], e0, e1);
        unpack2(al[s], r0, r1);
        float s0 = __expf(-e0), s1 = __expf(-e1);
        ag[s] = pack2(s0, s1);           // reuse as strength storage
        float ss = s0 + s1;
        float pp = s0 * r0 + s1 * r1;
        #pragma unroll
        for (int off = 16; off > 0; off >>= 1) {
            ss += __shfl_xor_sync(0xffffffffu, ss, off);
            pp += __shfl_xor_sync(0xffffffffu, pp, off);
        }
        if (lane == 0) sts64(redA + (s * 4 + half * 2) * 4, ss, pp);
        float s0v, s1v;
        unpack2(ag[s], s0v, s1v);
        *reinterpret_cast<float2*>(&strengths[(n0 + s) * R + rb]) =
            make_float2(s0v, s1v);
    }
    __syncthreads();

    // ---- combine halves, write normalized + pred
    #pragma unroll
    for (int s = 0; s < S; s++) {
        float4 rr = *reinterpret_cast<const float4*>(
            &smem[OFF_RED / 4 + g * 32 + s * 4]);   // {ss0,pp0,ss1,pp1}
        float inv = 1.0f / ((rr.x + rr.z) + 1e-8f);
        float s0, s1;
        unpack2(ag[s], s0, s1);
        *reinterpret_cast<float2*>(&normalized[(n0 + s) * R + rb]) =
            make_float2(s0 * inv, s1 * inv);
        if (half == 0 && lane == 0)
            pred[n0 + s] = (rr.y + rr.w) * inv;
    }
}

extern "C" void kernel_launch(void* const* d_in, const int* in_sizes, int n_in,
                              void* d_out, int out_size) {
    const float* X = (const float*)d_in[0];
    const float* a = (const float*)d_in[1];
    const float* b = (const float*)d_in[2];
    const float* c = (const float*)d_in[3];

    float* out        = (float*)d_out;
    float* pred       = out;
    float* strengths  = out + NS;
    float* normalized = out + NS + NS * R;

    static bool attr_set = false;
    if (!attr_set) {
        cudaFuncSetAttribute(anfis_main,
                             cudaFuncAttributeMaxDynamicSharedMemorySize,
                             SMEM_BYTES);
        attr_set = true;
    }

    anfis_precomp<<<R, D>>>(a, b, c);
    anfis_main<<<NS / S / GPB, 256, SMEM_BYTES>>>(X, pred, strengths, normalized);
}

// round 6
// speedup vs baseline: 2.7582x; 1.1316x over previous
#include <cuda_runtime.h>
#include <cstdint>

#define NS 65536
#define D  32
#define R  128
#define S  8          // samples per group
#define GPB 4         // groups per block (2 warps each -> 8 warps, 256 threads)

typedef unsigned long long ull;

// smem layout (bytes):
//   sWV  [D][64 pairs][w0,w1,v0,v1] @ 0       (32768)
//   red  [GPB][S][2 halves][2]      @ 32768   (512)
//   xt   [GPB][D][S] ull            @ 33280   (8192)  x duplicated (x,x)
#define OFF_RED 32768
#define OFF_X   33280
#define SMEM_BYTES (33280 + GPB * D * S * 8)

__device__ float gWV[D * 64 * 4];   // interleaved (w0,w1,v0,v1) per rule pair
__device__ float gCt[D * R];        // c transposed [d][r]
__device__ float gBias[R];

__global__ void anfis_precomp(const float* __restrict__ a,
                              const float* __restrict__ b,
                              const float* __restrict__ c) {
    int r = blockIdx.x, d = threadIdx.x;
    float av = a[r * D + d];
    float bv = fmaxf(b[r * D + d], 1e-8f);
    float w  = 0.70710678118654752f / bv;
    int p = r >> 1, e = r & 1;
    gWV[(d * 64 + p) * 4 + e]     = w;
    gWV[(d * 64 + p) * 4 + 2 + e] = -w * av;
    gCt[d * R + r] = c[r * (D + 1) + d];
    if (d == 0) gBias[r] = c[r * (D + 1) + D];
}

__device__ __forceinline__ ull fma2(ull a, ull b, ull c) {
    ull d;
    asm("fma.rn.f32x2 %0, %1, %2, %3;" : "=l"(d) : "l"(a), "l"(b), "l"(c));
    return d;
}
#define LDS128I(base, imm, lo, hi) \
    asm volatile("ld.shared.v2.u64 {%0, %1}, [%2 + %3];" \
                 : "=l"(lo), "=l"(hi) : "r"(base), "n"(imm))
#define LDGC(ptr, imm, v) \
    asm volatile("ld.global.nc.u64 %0, [%1 + %2];" \
                 : "=l"(v) : "l"(ptr), "n"(imm))
__device__ __forceinline__ void sts64(uint32_t addr, float lo, float hi) {
    asm volatile("st.shared.v2.f32 [%0], {%1, %2};" :: "r"(addr), "f"(lo), "f"(hi));
}
__device__ __forceinline__ void unpack2(ull v, float& lo, float& hi) {
    asm("mov.b64 {%0, %1}, %2;" : "=f"(lo), "=f"(hi) : "l"(v));
}
__device__ __forceinline__ ull pack2(float lo, float hi) {
    ull v;
    asm("mov.b64 %0, {%1, %2};" : "=l"(v) : "f"(lo), "f"(hi));
    return v;
}

// one fully-unrolled d-step: immediates only, no address arithmetic
#define SUB(xoff, AGa, ALa, AGb, ALb)                              \
    {                                                              \
        ull xa, xc, ua, uc;                                        \
        LDS128I(xb, (xoff), xa, xc);                               \
        ua = fma2(w01, xa, v01);                                   \
        AGa = fma2(ua, ua, AGa);                                   \
        ALa = fma2(c01, xa, ALa);                                  \
        uc = fma2(w01, xc, v01);                                   \
        AGb = fma2(uc, uc, AGb);                                   \
        ALb = fma2(c01, xc, ALb);                                  \
    }
#define STEP(d)                                                    \
    {                                                              \
        ull w01, v01, c01;                                         \
        LDS128I(wvA, (d) * 1024, w01, v01);                        \
        LDGC(cptr, (d) * 512, c01);                                \
        SUB((d) * 64 + 0,  ag0, al0, ag1, al1)                     \
        SUB((d) * 64 + 16, ag2, al2, ag3, al3)                     \
        SUB((d) * 64 + 32, ag4, al4, ag5, al5)                     \
        SUB((d) * 64 + 48, ag6, al6, ag7, al7)                     \
    }

#define EPI(s, AG, AL)                                             \
    {                                                              \
        float e0, e1, r0, r1;                                      \
        unpack2(AG, e0, e1);                                       \
        unpack2(AL, r0, r1);                                       \
        float s0 = __expf(-e0), s1 = __expf(-e1);                  \
        AG = pack2(s0, s1);                                        \
        float ss = s0 + s1, pp = s0 * r0 + s1 * r1;                \
        _Pragma("unroll")                                          \
        for (int off = 16; off > 0; off >>= 1) {                   \
            ss += __shfl_xor_sync(0xffffffffu, ss, off);           \
            pp += __shfl_xor_sync(0xffffffffu, pp, off);           \
        }                                                          \
        if (lane == 0) sts64(redA + (s) * 16 + half * 8, ss, pp);  \
        *reinterpret_cast<float2*>(&strengths[(n0 + (s)) * R + rb]) = \
            make_float2(s0, s1);                                   \
    }

#define FIN(s, AG)                                                 \
    {                                                              \
        float4 rr = *reinterpret_cast<const float4*>(              \
            &smem[OFF_RED / 4 + g * 32 + (s) * 4]);                \
        float inv = 1.0f / ((rr.x + rr.z) + 1e-8f);                \
        float s0, s1;                                              \
        unpack2(AG, s0, s1);                                       \
        *reinterpret_cast<float2*>(&normalized[(n0 + (s)) * R + rb]) = \
            make_float2(s0 * inv, s1 * inv);                       \
        if (half == 0 && lane == 0) pred[n0 + (s)] = (rr.y + rr.w) * inv; \
    }

__global__ void __launch_bounds__(256, 4)
anfis_main(const float* __restrict__ X,
           float* __restrict__ pred,
           float* __restrict__ strengths,
           float* __restrict__ normalized) {
    extern __shared__ float smem[];
    uint32_t sbase;
    {
        uint64_t t;
        asm("cvta.to.shared.u64 %0, %1;" : "=l"(t) : "l"(smem));
        sbase = (uint32_t)t;
    }

    // fill wv table (8192 floats) with float4 copies
    {
        const float4* src = reinterpret_cast<const float4*>(gWV);
        float4* dst = reinterpret_cast<float4*>(smem);
        for (int i = threadIdx.x; i < D * 64; i += blockDim.x)
            dst[i] = src[i];
    }
    // stage X: thread t handles float4 j=t&63 of group g=t>>6
    {
        int gg  = threadIdx.x >> 6;
        int j   = threadIdx.x & 63;
        int row = j >> 3;
        int seg = j & 7;
        int n0g = (blockIdx.x * GPB + gg) * S;
        float4 v = *reinterpret_cast<const float4*>(X + (n0g + row) * D + seg * 4);
        uint32_t base = sbase + OFF_X + gg * (D * S * 8) + ((seg * 4) * S + row) * 8;
        sts64(base + 0 * S * 8, v.x, v.x);
        sts64(base + 1 * S * 8, v.y, v.y);
        sts64(base + 2 * S * 8, v.z, v.z);
        sts64(base + 3 * S * 8, v.w, v.w);
    }
    __syncthreads();

    const int lane = threadIdx.x & 31;
    const int warp = threadIdx.x >> 5;
    const int g    = warp >> 1;
    const int half = warp & 1;
    const int rb   = half * 64 + lane * 2;
    const int n0   = (blockIdx.x * GPB + g) * S;

    const uint32_t wvA  = sbase + (half * 32 + lane) * 16;
    const uint32_t xb   = sbase + OFF_X + g * (D * S * 8);
    const uint32_t redA = sbase + OFF_RED + g * 128;
    const float* cptr = gCt + rb;

    ull bb;
    LDGC(gBias + rb, 0, bb);
    ull ag0 = 0, ag1 = 0, ag2 = 0, ag3 = 0, ag4 = 0, ag5 = 0, ag6 = 0, ag7 = 0;
    ull al0 = bb, al1 = bb, al2 = bb, al3 = bb, al4 = bb, al5 = bb, al6 = bb, al7 = bb;

    STEP(0)  STEP(1)  STEP(2)  STEP(3)  STEP(4)  STEP(5)  STEP(6)  STEP(7)
    STEP(8)  STEP(9)  STEP(10) STEP(11) STEP(12) STEP(13) STEP(14) STEP(15)
    STEP(16) STEP(17) STEP(18) STEP(19) STEP(20) STEP(21) STEP(22) STEP(23)
    STEP(24) STEP(25) STEP(26) STEP(27) STEP(28) STEP(29) STEP(30) STEP(31)

    EPI(0, ag0, al0) EPI(1, ag1, al1) EPI(2, ag2, al2) EPI(3, ag3, al3)
    EPI(4, ag4, al4) EPI(5, ag5, al5) EPI(6, ag6, al6) EPI(7, ag7, al7)
    __syncthreads();
    FIN(0, ag0) FIN(1, ag1) FIN(2, ag2) FIN(3, ag3)
    FIN(4, ag4) FIN(5, ag5) FIN(6, ag6) FIN(7, ag7)
}

extern "C" void kernel_launch(void* const* d_in, const int* in_sizes, int n_in,
                              void* d_out, int out_size) {
    const float* X = (const float*)d_in[0];
    const float* a = (const float*)d_in[1];
    const float* b = (const float*)d_in[2];
    const float* c = (const float*)d_in[3];

    float* out        = (float*)d_out;
    float* pred       = out;
    float* strengths  = out + NS;
    float* normalized = out + NS + NS * R;

    static bool attr_set = false;
    if (!attr_set) {
        cudaFuncSetAttribute(anfis_main,
                             cudaFuncAttributeMaxDynamicSharedMemorySize,
                             SMEM_BYTES);
        attr_set = true;
    }

    anfis_precomp<<<R, D>>>(a, b, c);
    anfis_main<<<NS / S / GPB, 256, SMEM_BYTES>>>(X, pred, strengths, normalized);
}